// round 8
// baseline (speedup 1.0000x reference)
#include <cuda_runtime.h>
#include <cuda_bf16.h>
#include <cstdint>

#define N_NODES 20000
#define BATCH 512
#define EMBED_DIM 32
#define NUM_SAMPLES 5001
#define TD_MAX 5000.0f

#define TILE 256                  // nodes per lambda block (1 per thread)
#define NTILES ((N_NODES + TILE - 1) / TILE)   // 79
#define BG 16                     // batch rows per lambda block
#define BGROUPS (BATCH / BG)      // 32
#define LAMBDA_BLOCKS (NTILES * BGROUPS)       // 2528
#define TOTAL_BLOCKS (LAMBDA_BLOCKS + BATCH)   // 3040
#define CHUNK 20                  // 256*20 >= 5001

#define L2E 1.4426950408889634f
#define LN2 0.6931471805599453f

// ps * softplus(x), psln2 = ps*ln2 prefolded
__device__ __forceinline__ float sp_scaled(float x, float ps, float psln2) {
    float e  = exp2f(-L2E * fabsf(x));
    float lg = __log2f(1.0f + e);
    return fmaf(lg, psln2, ps * fmaxf(x, 0.0f));
}

__device__ __forceinline__ float dot32(const float* __restrict__ a,
                                       const float* __restrict__ w) {
    const float4* a4 = (const float4*)a;
    const float4* w4 = (const float4*)w;
    float s = 0.f;
    #pragma unroll
    for (int q = 0; q < 8; q++) {
        float4 r = __ldg(a4 + q);
        float4 c = __ldg(w4 + q);
        s = fmaf(r.x, c.x, fmaf(r.y, c.y, fmaf(r.z, c.z, fmaf(r.w, c.w, s))));
    }
    return s;
}

// ---------------------------------------------------------------------------
// Single fused kernel, fine-grained grid (3040 blocks) for wave balance.
//  blockIdx.x < LAMBDA_BLOCKS : lambda tile (tile = id%79, bgroup = id/79)
//  else                       : return_time scan for b = blockIdx.x - 2528
// ---------------------------------------------------------------------------
__global__ void __launch_bounds__(256, 6) decoder_kernel(
    float* __restrict__ out,
    const float* __restrict__ emb,
    const int*   __restrict__ assoc,
    const int*   __restrict__ src,
    const int*   __restrict__ pdst,
    const float* __restrict__ last_update,
    const float* __restrict__ cur_time,
    const int*   __restrict__ et,
    const float* __restrict__ W0,
    const float* __restrict__ b0,
    const float* __restrict__ W1,
    const float* __restrict__ b1,
    const float* __restrict__ psi,
    const float* __restrict__ alpha,
    const float* __restrict__ w_t)
{
    int t = threadIdx.x;

    float ps0 = __ldg(psi);
    float ps1 = __ldg(psi + 1);
    float inv0 = 1.0f / (ps0 + 1e-7f);
    float inv1 = 1.0f / (ps1 + 1e-7f);

    if (blockIdx.x < LAMBDA_BLOCKS) {
        // ================= lambda block =================
        int tile = blockIdx.x % NTILES;
        int bg   = blockIdx.x / NTILES;
        int node = tile * TILE + t;
        bool live = (node < N_NODES);

        __shared__ float4 sm_c[BG];    // (cs*inv, cd*inv, e_as_float, ps)

        // per-thread projections for ONE node, pre-scaled by inv_e
        float u0 = 0.f, v0 = 0.f, u1 = 0.f, v1 = 0.f;
        if (live) {
            const float* row = emb + (size_t)node * EMBED_DIM;
            u0 = dot32(row, W0)      * inv0;
            v0 = dot32(row, W0 + 32) * inv0;
            u1 = dot32(row, W1)      * inv1;
            v1 = dot32(row, W1 + 32) * inv1;
        }

        // batch scalars for this block's 16 b's (threads 0..15)
        if (t < BG) {
            int b = bg * BG + t;
            int e = (__ldg(et + b) > 0) ? 1 : 0;
            int is = __ldg(assoc + __ldg(src + b));
            int id = __ldg(assoc + __ldg(pdst + b));
            const float* Wu = e ? W1 : W0;
            float bb = e ? __ldg(b1) : __ldg(b0);
            float s = dot32(emb + (size_t)is * EMBED_DIM, Wu)      + bb;
            float d = dot32(emb + (size_t)id * EMBED_DIM, Wu + 32) + bb;
            float al = __ldg(alpha + e), w = __ldg(w_t + e);
            float inv = e ? inv1 : inv0;
            float ct  = __ldg(cur_time + b);
            float tds = (ct - __ldg(last_update + is)) * (1.0f / TD_MAX);
            float tdd = (ct - __ldg(last_update + id)) * (1.0f / TD_MAX);
            sm_c[t] = make_float4((s + al * __expf(-w * tds)) * inv,
                                  (d + al * __expf(-w * tdd)) * inv,
                                  (float)e,
                                  e ? ps1 : ps0);
        }
        __syncthreads();

        if (!live) return;

        float du = u1 - u0;     // e-interpolation deltas (e is exactly 0 or 1)
        float dv = v1 - v0;
        float* outs = out + (size_t)(bg * BG) * N_NODES + node;
        float* outd = outs + (size_t)BATCH * N_NODES;

        #pragma unroll
        for (int bb = 0; bb < BG; bb++) {
            float4 c    = sm_c[bb];
            float un    = fmaf(c.z, du, u0);
            float vn    = fmaf(c.z, dv, v0);
            float ps    = c.w;
            float psln2 = ps * LN2;

            float ls = sp_scaled(vn + c.x, ps, psln2);   // lambda_src
            float ld = sp_scaled(un + c.y, ps, psln2);   // lambda_dst
            outs[0] = ls;
            outd[0] = ld;
            outs += N_NODES;
            outd += N_NODES;
        }
        return;
    }

    // ================= return_time block (one b) =================
    int b = blockIdx.x - LAMBDA_BLOCKS;

    __shared__ float sm_bp[4];   // gbi, ali, wtn, ps

    if (t < 32) {
        int e = (__ldg(et + b) > 0) ? 1 : 0;
        int is = __ldg(assoc + __ldg(src + b));
        int id = __ldg(assoc + __ldg(pdst + b));
        const float* Wu = e ? W1 : W0;
        float sp = __ldg(emb + (size_t)is * EMBED_DIM + t) * __ldg(Wu + t);
        float dp = __ldg(emb + (size_t)id * EMBED_DIM + t) * __ldg(Wu + 32 + t);
        #pragma unroll
        for (int o = 16; o > 0; o >>= 1) {
            sp += __shfl_down_sync(0xffffffffu, sp, o);
            dp += __shfl_down_sync(0xffffffffu, dp, o);
        }
        if (t == 0) {
            float bb = e ? __ldg(b1) : __ldg(b0);
            float inv = e ? inv1 : inv0;
            sm_bp[0] = (sp + dp + bb) * inv;
            sm_bp[1] = __ldg(alpha + e) * inv;
            sm_bp[2] = __ldg(w_t + e) * (L2E / TD_MAX);
            sm_bp[3] = e ? ps1 : ps0;
        }
    }
    __syncthreads();

    float gbi = sm_bp[0], ali = sm_bp[1], wtn = sm_bp[2], ps = sm_bp[3];
    float psln2 = ps * LN2;

    int i0 = t * CHUNK;
    float loc[CHUNK];
    float s = 0.f;
    #pragma unroll
    for (int k = 0; k < CHUNK; k++) {
        int i = i0 + k;
        float inten = 0.f;
        if (i < NUM_SAMPLES) {
            float exc = exp2f(-wtn * (float)i);
            inten = sp_scaled(fmaf(exc, ali, gbi), ps, psln2);
        }
        loc[k] = inten;
        s += inten;
    }

    // Block exclusive scan of per-thread sums
    unsigned m = 0xffffffffu;
    float v = s;
    #pragma unroll
    for (int o = 1; o < 32; o <<= 1) {
        float n = __shfl_up_sync(m, v, o);
        if ((t & 31) >= o) v += n;
    }
    __shared__ float wsum[8];
    if ((t & 31) == 31) wsum[t >> 5] = v;
    __syncthreads();
    if (t < 8) {
        float w = wsum[t];
        #pragma unroll
        for (int o = 1; o < 8; o <<= 1) {
            float n = __shfl_up_sync(0xffu, w, o);
            if (t >= o) w += n;
        }
        wsum[t] = w;
    }
    __syncthreads();
    float excl = (v - s) + ((t >= 32) ? wsum[(t >> 5) - 1] : 0.f);

    float run = excl;
    float acc = 0.f;
    #pragma unroll
    for (int k = 0; k < CHUNK; k++) {
        int i = i0 + k;
        if (i < NUM_SAMPLES) {
            run += loc[k];                          // integral_i (TIMESTEP=1)
            float dens = loc[k] * exp2f(-L2E * run);
            float wgt = (i == NUM_SAMPLES - 1) ? 0.5f : 1.0f;  // i==0 term is 0
            acc = fmaf(wgt * (float)i, dens, acc);
        }
    }

    #pragma unroll
    for (int o = 16; o > 0; o >>= 1) acc += __shfl_down_sync(m, acc, o);
    __shared__ float rsum[8];
    if ((t & 31) == 0) rsum[t >> 5] = acc;
    __syncthreads();
    if (t == 0) {
        float tot = 0.f;
        #pragma unroll
        for (int wgrp = 0; wgrp < 8; wgrp++) tot += rsum[wgrp];
        out[(size_t)2 * BATCH * N_NODES + b] = tot;
    }
}

// ---------------------------------------------------------------------------
extern "C" void kernel_launch(void* const* d_in, const int* in_sizes, int n_in,
                              void* d_out, int out_size)
{
    (void)in_sizes; (void)n_in; (void)out_size;
    const float* emb   = (const float*)d_in[0];
    const int*   assoc = (const int*)  d_in[1];
    const int*   src   = (const int*)  d_in[2];
    const int*   pdst  = (const int*)  d_in[3];
    const float* lu    = (const float*)d_in[5];
    const float* ct    = (const float*)d_in[6];
    const int*   et    = (const int*)  d_in[7];
    const float* W0    = (const float*)d_in[8];
    const float* b0    = (const float*)d_in[9];
    const float* W1    = (const float*)d_in[10];
    const float* b1    = (const float*)d_in[11];
    const float* psi   = (const float*)d_in[12];
    const float* alpha = (const float*)d_in[13];
    const float* w_t   = (const float*)d_in[14];

    decoder_kernel<<<TOTAL_BLOCKS, 256>>>((float*)d_out, emb, assoc, src, pdst,
                                          lu, ct, et, W0, b0, W1, b1,
                                          psi, alpha, w_t);
}

// round 9
// speedup vs baseline: 1.9386x; 1.9386x over previous
#include <cuda_runtime.h>
#include <cuda_bf16.h>
#include <cstdint>

#define N_NODES 20000
#define BATCH 512
#define EMBED_DIM 32
#define NUM_SAMPLES 5001
#define TD_MAX 5000.0f

#define N4 5000                   // float4 columns per row
#define XTILES 20                 // x-tiles of 256 float4 (covers 5120 >= 5000)
#define BG 8                      // batch rows per lambda block
#define BGROUPS (BATCH / BG)      // 64
#define LAMBDA_BLOCKS (XTILES * BGROUPS)      // 1280
#define TOTAL_BLOCKS (LAMBDA_BLOCKS + BATCH)  // 1792
#define CHUNK 20                  // 256*20 >= 5001

#define L2E 1.4426950408889634f
#define LN2 0.6931471805599453f

// Scratch (device globals; allocation is forbidden)
__device__ float4 d_nodeP[N_NODES];  // (u0*inv0, v0*inv0, u1*inv1-u0*inv0, v1*inv1-v0*inv0)
__device__ float4 d_bc[BATCH];       // (cs*inv_e, cd*inv_e, e, ps_e)       for lambda
__device__ float4 d_bc2[BATCH];      // (gb*inv_e, al*inv_e, w*L2E/TD_MAX, ps_e) for rt

// ps * softplus(x), psln2 = ps*ln2 prefolded
__device__ __forceinline__ float sp_scaled(float x, float ps, float psln2) {
    float e  = exp2f(-L2E * fabsf(x));
    float lg = __log2f(1.0f + e);
    return fmaf(lg, psln2, ps * fmaxf(x, 0.0f));
}

__device__ __forceinline__ float dot32(const float* __restrict__ a,
                                       const float* __restrict__ w) {
    const float4* a4 = (const float4*)a;
    const float4* w4 = (const float4*)w;
    float s = 0.f;
    #pragma unroll
    for (int q = 0; q < 8; q++) {
        float4 r = __ldg(a4 + q);
        float4 c = __ldg(w4 + q);
        s = fmaf(r.x, c.x, fmaf(r.y, c.y, fmaf(r.z, c.z, fmaf(r.w, c.w, s))));
    }
    return s;
}

// ---------------------------------------------------------------------------
// Kernel 1: per-node projections (1 thread/node, all 4 dots in one row pass)
//           + per-batch constant tables (threads 0..511)
// ---------------------------------------------------------------------------
__global__ void __launch_bounds__(256) prep_kernel(
    const float* __restrict__ emb,
    const int*   __restrict__ assoc,
    const int*   __restrict__ src,
    const int*   __restrict__ pdst,
    const float* __restrict__ last_update,
    const float* __restrict__ cur_time,
    const int*   __restrict__ et,
    const float* __restrict__ W0,
    const float* __restrict__ b0,
    const float* __restrict__ W1,
    const float* __restrict__ b1,
    const float* __restrict__ psi,
    const float* __restrict__ alpha,
    const float* __restrict__ w_t)
{
    int gid = blockIdx.x * blockDim.x + threadIdx.x;

    float ps0 = __ldg(psi);
    float ps1 = __ldg(psi + 1);
    float inv0 = 1.0f / (ps0 + 1e-7f);
    float inv1 = 1.0f / (ps1 + 1e-7f);

    if (gid < N_NODES) {
        const float4* row = (const float4*)(emb + (size_t)gid * EMBED_DIM);
        const float4* w0u = (const float4*)W0;
        const float4* w0v = (const float4*)(W0 + 32);
        const float4* w1u = (const float4*)W1;
        const float4* w1v = (const float4*)(W1 + 32);
        float u0 = 0.f, v0 = 0.f, u1 = 0.f, v1 = 0.f;
        #pragma unroll
        for (int q = 0; q < 8; q++) {
            float4 r  = __ldg(row + q);
            float4 a0 = __ldg(w0u + q), c0 = __ldg(w0v + q);
            float4 a1 = __ldg(w1u + q), c1 = __ldg(w1v + q);
            u0 = fmaf(r.x, a0.x, fmaf(r.y, a0.y, fmaf(r.z, a0.z, fmaf(r.w, a0.w, u0))));
            v0 = fmaf(r.x, c0.x, fmaf(r.y, c0.y, fmaf(r.z, c0.z, fmaf(r.w, c0.w, v0))));
            u1 = fmaf(r.x, a1.x, fmaf(r.y, a1.y, fmaf(r.z, a1.z, fmaf(r.w, a1.w, u1))));
            v1 = fmaf(r.x, c1.x, fmaf(r.y, c1.y, fmaf(r.z, c1.z, fmaf(r.w, c1.w, v1))));
        }
        float u0i = u0 * inv0, v0i = v0 * inv0;
        d_nodeP[gid] = make_float4(u0i, v0i, u1 * inv1 - u0i, v1 * inv1 - v0i);
    }

    if (gid < BATCH) {
        int b = gid;
        int e = (__ldg(et + b) > 0) ? 1 : 0;
        int is = __ldg(assoc + __ldg(src + b));
        int id = __ldg(assoc + __ldg(pdst + b));
        const float* Wu = e ? W1 : W0;
        float bb = e ? __ldg(b1) : __ldg(b0);
        float s = dot32(emb + (size_t)is * EMBED_DIM, Wu)      + bb;
        float d = dot32(emb + (size_t)id * EMBED_DIM, Wu + 32) + bb;
        float al = __ldg(alpha + e), w = __ldg(w_t + e);
        float ps = e ? ps1 : ps0;
        float inv = e ? inv1 : inv0;
        float ct  = __ldg(cur_time + b);
        float tds = (ct - __ldg(last_update + is)) * (1.0f / TD_MAX);
        float tdd = (ct - __ldg(last_update + id)) * (1.0f / TD_MAX);
        d_bc[b]  = make_float4((s + al * __expf(-w * tds)) * inv,
                               (d + al * __expf(-w * tdd)) * inv,
                               (float)e, ps);
        d_bc2[b] = make_float4((s + d - bb) * inv,
                               al * inv,
                               w * (L2E / TD_MAX),
                               ps);
    }
}

// ---------------------------------------------------------------------------
// Kernel 2: main. blockIdx.x < 1280 -> lambda (x-tile, 8 b's, reg-cached nodes)
//                 else              -> return_time scan for one b
// No smem / no __syncthreads in the lambda path.
// ---------------------------------------------------------------------------
__global__ void __launch_bounds__(256) main_kernel(float* __restrict__ out)
{
    int t = threadIdx.x;

    if (blockIdx.x < LAMBDA_BLOCKS) {
        int tile = blockIdx.x % XTILES;
        int bg   = blockIdx.x / XTILES;      // [0, 64)
        int x    = tile * 256 + t;           // float4 column
        if (x >= N4) return;

        // node data for 4 nodes, loaded ONCE
        float4 P0 = __ldg(&d_nodeP[4 * x + 0]);
        float4 P1 = __ldg(&d_nodeP[4 * x + 1]);
        float4 P2 = __ldg(&d_nodeP[4 * x + 2]);
        float4 P3 = __ldg(&d_nodeP[4 * x + 3]);

        float* outs = out + (size_t)(bg * BG) * N_NODES + 4 * x;
        float* outd = outs + (size_t)BATCH * N_NODES;

        #pragma unroll
        for (int bb = 0; bb < BG; bb++) {
            float4 c = __ldg(&d_bc[bg * BG + bb]);   // warp-uniform broadcast
            float ps    = c.w;
            float psln2 = ps * LN2;

            float4 ls, ld;
            // node j: un = fma(e, du, u0i), vn = fma(e, dv, v0i)
            ls.x = sp_scaled(fmaf(c.z, P0.w, P0.y) + c.x, ps, psln2);
            ld.x = sp_scaled(fmaf(c.z, P0.z, P0.x) + c.y, ps, psln2);
            ls.y = sp_scaled(fmaf(c.z, P1.w, P1.y) + c.x, ps, psln2);
            ld.y = sp_scaled(fmaf(c.z, P1.z, P1.x) + c.y, ps, psln2);
            ls.z = sp_scaled(fmaf(c.z, P2.w, P2.y) + c.x, ps, psln2);
            ld.z = sp_scaled(fmaf(c.z, P2.z, P2.x) + c.y, ps, psln2);
            ls.w = sp_scaled(fmaf(c.z, P3.w, P3.y) + c.x, ps, psln2);
            ld.w = sp_scaled(fmaf(c.z, P3.z, P3.x) + c.y, ps, psln2);

            *(float4*)outs = ls;
            *(float4*)outd = ld;
            outs += N_NODES;
            outd += N_NODES;
        }
        return;
    }

    // ================= return_time block (one b) =================
    int b = blockIdx.x - LAMBDA_BLOCKS;
    float4 c2 = __ldg(&d_bc2[b]);
    float gbi = c2.x, ali = c2.y, wtn = c2.z, ps = c2.w;
    float psln2 = ps * LN2;

    int i0 = t * CHUNK;
    float loc[CHUNK];
    float s = 0.f;
    #pragma unroll
    for (int k = 0; k < CHUNK; k++) {
        int i = i0 + k;
        float inten = 0.f;
        if (i < NUM_SAMPLES) {
            float exc = exp2f(-wtn * (float)i);
            inten = sp_scaled(fmaf(exc, ali, gbi), ps, psln2);
        }
        loc[k] = inten;
        s += inten;
    }

    // Block exclusive scan of per-thread sums
    unsigned m = 0xffffffffu;
    float v = s;
    #pragma unroll
    for (int o = 1; o < 32; o <<= 1) {
        float n = __shfl_up_sync(m, v, o);
        if ((t & 31) >= o) v += n;
    }
    __shared__ float wsum[8];
    if ((t & 31) == 31) wsum[t >> 5] = v;
    __syncthreads();
    if (t < 8) {
        float w = wsum[t];
        #pragma unroll
        for (int o = 1; o < 8; o <<= 1) {
            float n = __shfl_up_sync(0xffu, w, o);
            if (t >= o) w += n;
        }
        wsum[t] = w;
    }
    __syncthreads();
    float excl = (v - s) + ((t >= 32) ? wsum[(t >> 5) - 1] : 0.f);

    float run = excl;
    float acc = 0.f;
    #pragma unroll
    for (int k = 0; k < CHUNK; k++) {
        int i = i0 + k;
        if (i < NUM_SAMPLES) {
            run += loc[k];                          // integral_i (TIMESTEP=1)
            float dens = loc[k] * exp2f(-L2E * run);
            float wgt = (i == NUM_SAMPLES - 1) ? 0.5f : 1.0f;  // i==0 term is 0
            acc = fmaf(wgt * (float)i, dens, acc);
        }
    }

    #pragma unroll
    for (int o = 16; o > 0; o >>= 1) acc += __shfl_down_sync(m, acc, o);
    __shared__ float rsum[8];
    if ((t & 31) == 0) rsum[t >> 5] = acc;
    __syncthreads();
    if (t == 0) {
        float tot = 0.f;
        #pragma unroll
        for (int wgrp = 0; wgrp < 8; wgrp++) tot += rsum[wgrp];
        out[(size_t)2 * BATCH * N_NODES + b] = tot;
    }
}

// ---------------------------------------------------------------------------
extern "C" void kernel_launch(void* const* d_in, const int* in_sizes, int n_in,
                              void* d_out, int out_size)
{
    (void)in_sizes; (void)n_in; (void)out_size;
    const float* emb   = (const float*)d_in[0];
    const int*   assoc = (const int*)  d_in[1];
    const int*   src   = (const int*)  d_in[2];
    const int*   pdst  = (const int*)  d_in[3];
    const float* lu    = (const float*)d_in[5];
    const float* ct    = (const float*)d_in[6];
    const int*   et    = (const int*)  d_in[7];
    const float* W0    = (const float*)d_in[8];
    const float* b0    = (const float*)d_in[9];
    const float* W1    = (const float*)d_in[10];
    const float* b1    = (const float*)d_in[11];
    const float* psi   = (const float*)d_in[12];
    const float* alpha = (const float*)d_in[13];
    const float* w_t   = (const float*)d_in[14];

    prep_kernel<<<(N_NODES + 255) / 256, 256>>>(emb, assoc, src, pdst, lu, ct, et,
                                                W0, b0, W1, b1, psi, alpha, w_t);

    main_kernel<<<TOTAL_BLOCKS, 256>>>((float*)d_out);
}